// round 5
// baseline (speedup 1.0000x reference)
#include <cuda_runtime.h>
#include <cstdint>

#define DD 128
#define KK 32
#define NTHREADS 512
#define NBLOCKS 444
#define NCELLS 128

// ---- shared memory layout ----
// s_xpos : [35][128] knots (rows 33,34 = +INF pad), bank = dim mod 32 = lane
// s_ys   : [33][128] float2 {ypos, slope}  (LDS.64, 2-phase conflict-free)
// s_lut  : [128][128] uint8 bin-base per (cell, dim); byte loads conflict-free
#define XPOS_OFF 0
#define YS_OFF   (35 * DD)
#define LUT_BYTE_OFF ((YS_OFF + 2 * 33 * DD) * 4)
#define SMEM_BYTES (LUT_BYTE_OFF + NCELLS * DD)

__global__ void __launch_bounds__(NTHREADS, 3)
rqs_kernel(const float* __restrict__ x,
           const float* __restrict__ sp,
           float* __restrict__ y_out,
           float* __restrict__ ld_out,
           int n_rows)
{
    extern __shared__ float sm[];
    float*   s_xpos = sm + XPOS_OFF;
    float2*  s_ys   = (float2*)(sm + YS_OFF);
    uint8_t* s_lut  = (uint8_t*)sm + LUT_BYTE_OFF;

    const int tid = threadIdx.x;
    const float TOTAL_M = 10.0f - KK * 1e-4f;

    // ---- per-block table build (redundant across blocks, trivially cheap) ----
    if (tid < DD) {
        const int d = tid;
        const float* uw = sp + d * (3 * KK + 1);
        float m = -1e30f;
        #pragma unroll 1
        for (int k = 0; k < KK; k++) m = fmaxf(m, uw[k]);
        float s = 0.f;
        #pragma unroll 1
        for (int k = 0; k < KK; k++) s += __expf(uw[k] - m);
        float scale = TOTAL_M / s;
        float run = -5.0f;
        s_xpos[d] = run;
        #pragma unroll 1
        for (int k = 0; k < KK; k++) {
            float w = __expf(uw[k] - m) * scale + 1e-4f;
            run += w;
            s_xpos[(k + 1) * DD + d] = run;
        }
        s_xpos[33 * DD + d] = 1e30f;
        s_xpos[34 * DD + d] = 1e30f;
        // LUT: bin index of each cell's left edge (monotone walk)
        int k = 0;
        #pragma unroll 1
        for (int c = 0; c < NCELLS; c++) {
            float cl = c * 0.078125f - 5.0f;
            while (k < 31 && s_xpos[(k + 1) * DD + d] <= cl) k++;
            s_lut[c * DD + d] = (uint8_t)k;
        }
    } else if (tid < 2 * DD) {
        const int d = tid - DD;
        const float* uh = sp + d * (3 * KK + 1) + KK;
        const float* us = sp + d * (3 * KK + 1) + 2 * KK;
        float m = -1e30f;
        #pragma unroll 1
        for (int k = 0; k < KK; k++) m = fmaxf(m, uh[k]);
        float s = 0.f;
        #pragma unroll 1
        for (int k = 0; k < KK; k++) s += __expf(uh[k] - m);
        float scale = TOTAL_M / s;
        float run = -5.0f;
        s_ys[d].x = run;
        #pragma unroll 1
        for (int k = 0; k < KK; k++) {
            float h = __expf(uh[k] - m) * scale + 1e-4f;
            run += h;
            s_ys[(k + 1) * DD + d].x = run;
        }
        const float OFFS = 0.5411666430f;  // log(expm1(1 - 1e-4))
        #pragma unroll 1
        for (int k = 0; k <= KK; k++) {
            float v = us[k] + OFFS;
            float spv = fmaxf(v, 0.f) + __logf(1.f + __expf(-fabsf(v)));
            s_ys[k * DD + d].y = spv + 1e-4f;
        }
    }
    __syncthreads();

    // ---- main loop: one warp per row; x for the NEXT row is prefetched so
    //      the DRAM latency of the LDG is never on the critical path ----
    const int lane = tid & 31;
    const int warp = (blockIdx.x * NTHREADS + tid) >> 5;
    const int nwarps = gridDim.x * (NTHREADS >> 5);
    const float LN2 = 0.69314718055994531f;

    int row = warp;
    if (row >= n_rows) return;

    float xv4[4];
    {
        const float* xr = x + (size_t)row * DD + lane;
        #pragma unroll
        for (int j = 0; j < 4; j++) xv4[j] = xr[32 * j];
    }

    for (; row < n_rows; row += nwarps) {
        // prefetch next row (safe dummy address when past the end)
        const int nrow = row + nwarps;
        const size_t prow = (nrow < n_rows) ? (size_t)nrow : (size_t)row;
        const float* nxr = x + prow * DD + lane;
        float nx4[4];
        #pragma unroll
        for (int j = 0; j < 4; j++) nx4[j] = nxr[32 * j];

        float* yr = y_out + (size_t)row * DD + lane;
        float prod = 1.0f;

        #pragma unroll
        for (int j = 0; j < 4; j++) {
            const int d = lane + 32 * j;
            float xv = xv4[j];

            // level 1: LUT gives a conservative (low) bin base
            int c = (int)fmaf(xv, 12.8f, 64.0f) - 1;
            c = max(0, min(c, NCELLS - 1));
            int base = (int)s_lut[c * DD + d];

            // level 2: 3 parallel indicator loads refine to exact bin
            const float* xb = s_xpos + base * DD + d;
            float k1 = xb[1 * DD];
            float k2 = xb[2 * DD];
            float k3 = xb[3 * DD];
            int idx = base + (xv >= k1) + (xv >= k2) + (xv >= k3);
            idx = min(idx, KK - 1);

            // level 3: speculative fetch; register-only verify (fixup ~never)
            int o = idx * DD + d;
            float  x0  = s_xpos[o];
            float  x1  = s_xpos[o + DD];
            float2 ys0 = s_ys[o];
            float2 ys1 = s_ys[o + DD];
            while (idx < KK - 1 && xv >= x1) {   // cold path
                idx++; o += DD;
                x0 = x1; x1 = s_xpos[o + DD];
                ys0 = ys1; ys1 = s_ys[o + DD];
            }

            float y0 = ys0.x, s0 = ys0.y;
            float y1 = ys1.x, s1 = ys1.y;

            float ib;
            asm("rcp.approx.f32 %0, %1;" : "=f"(ib) : "f"(x1 - x0));
            float zr   = (xv - x0) * ib;
            float z    = fminf(fmaxf(zr, 0.f), 1.f);
            float bh   = y1 - y0;
            float bs   = bh * ib;
            float sqz  = z * z;
            float z1mz = z - sqz;
            float omz  = 1.f - z;
            float sq1  = omz * omz;

            float st  = (s0 + s1) - 2.f * bs;
            float den = fmaf(st, z1mz, bs);
            float num = bh * fmaf(s0, z1mz, bs * sqz);

            float r;
            asm("rcp.approx.f32 %0, %1;" : "=f"(r) : "f"(den));
            float yy = fmaf(num, r, y0);

            // derivative = bs^2 * arg / den^2 ; fold bs^2 via t = bs * (1/den)
            float arg = fmaf(s1, sqz, fmaf(s0, sq1, (bs + bs) * z1mz));
            float t   = bs * r;
            float deriv = (t * t) * arg;

            // out-of-range tails (P ~ 6e-7): linear extrapolation, edge slopes
            if (zr != z) {
                if (zr < 0.f) {
                    yy = fmaf(xv - x0, s0, y0);
                    deriv = s0;
                } else {
                    yy = fmaf(xv - x1, s1, y1);
                    deriv = s1;
                }
            }
            prod *= deriv;
            yr[32 * j] = yy;      // store immediately, no staging array
        }

        // rotate prefetch buffer
        #pragma unroll
        for (int j = 0; j < 4; j++) xv4[j] = nx4[j];

        // one LG2 per 4 elements, then warp-sum; scale by ln2 once per row
        float ls = __log2f(prod);
        #pragma unroll
        for (int off = 16; off; off >>= 1)
            ls += __shfl_xor_sync(0xffffffffu, ls, off);
        if (lane == 0) ld_out[row] = ls * LN2;
    }
}

extern "C" void kernel_launch(void* const* d_in, const int* in_sizes, int n_in,
                              void* d_out, int out_size)
{
    const float* x  = (const float*)d_in[0];
    const float* sp = (const float*)d_in[1];
    const int n_rows = in_sizes[0] / DD;

    float* y_out  = (float*)d_out;
    float* ld_out = (float*)d_out + (size_t)n_rows * DD;

    cudaFuncSetAttribute(rqs_kernel, cudaFuncAttributeMaxDynamicSharedMemorySize,
                         SMEM_BYTES);
    rqs_kernel<<<NBLOCKS, NTHREADS, SMEM_BYTES>>>(x, sp, y_out, ld_out, n_rows);
}

// round 6
// speedup vs baseline: 1.0668x; 1.0668x over previous
#include <cuda_runtime.h>
#include <cstdint>

#define DD 128
#define KK 32
#define NTHREADS 512
#define NBLOCKS 444
#define NCELLS 128

// ---- shared memory layout (floats) ----
// s_xpos : [35][128]  knots (rows 33,34 = +INF pad); bank = d mod 32 = lane
// s_ypos : [33][128]  knot y positions
// s_slp  : [33][128]  knot slopes
// s_lut  : [128][128] uint8 bin of each cell's left edge
// All per-bin fetches use ONE address register o = idx*128+d with immediate
// offsets (arrays are contiguous at constant offsets) -> minimal IMADs.
#define XPOS_OFF 0
#define YPOS_OFF (35 * DD)
#define SLP_OFF  (XPOS_OFF + (35 + 33) * DD)
#define LUT_BYTE_OFF ((SLP_OFF + 33 * DD) * 4)
#define SMEM_BYTES (LUT_BYTE_OFF + NCELLS * DD)

__global__ void __launch_bounds__(NTHREADS, 3)
rqs_kernel(const float* __restrict__ x,
           const float* __restrict__ sp,
           float* __restrict__ y_out,
           float* __restrict__ ld_out,
           int n_rows)
{
    extern __shared__ float sm[];
    float*   s_xpos = sm + XPOS_OFF;
    float*   s_ypos = sm + YPOS_OFF;
    float*   s_slp  = sm + SLP_OFF;
    uint8_t* s_lut  = (uint8_t*)sm + LUT_BYTE_OFF;

    const int tid = threadIdx.x;
    const float TOTAL_M = 10.0f - KK * 1e-4f;

    // ---- per-block table build (redundant across blocks, trivially cheap) ----
    if (tid < DD) {
        const int d = tid;
        const float* uw = sp + d * (3 * KK + 1);
        float m = -1e30f;
        #pragma unroll 1
        for (int k = 0; k < KK; k++) m = fmaxf(m, uw[k]);
        float s = 0.f;
        #pragma unroll 1
        for (int k = 0; k < KK; k++) s += __expf(uw[k] - m);
        float scale = TOTAL_M / s;
        float run = -5.0f;
        s_xpos[d] = run;
        #pragma unroll 1
        for (int k = 0; k < KK; k++) {
            float w = __expf(uw[k] - m) * scale + 1e-4f;
            run += w;
            s_xpos[(k + 1) * DD + d] = run;
        }
        s_xpos[33 * DD + d] = 1e30f;
        s_xpos[34 * DD + d] = 1e30f;
        // LUT: bin index of each cell's left edge (monotone walk)
        int k = 0;
        #pragma unroll 1
        for (int c = 0; c < NCELLS; c++) {
            float cl = c * 0.078125f - 5.0f;   // exact: 10/128 = 5*2^-6
            while (k < 31 && s_xpos[(k + 1) * DD + d] <= cl) k++;
            s_lut[c * DD + d] = (uint8_t)k;
        }
    } else if (tid < 2 * DD) {
        const int d = tid - DD;
        const float* uh = sp + d * (3 * KK + 1) + KK;
        const float* us = sp + d * (3 * KK + 1) + 2 * KK;
        float m = -1e30f;
        #pragma unroll 1
        for (int k = 0; k < KK; k++) m = fmaxf(m, uh[k]);
        float s = 0.f;
        #pragma unroll 1
        for (int k = 0; k < KK; k++) s += __expf(uh[k] - m);
        float scale = TOTAL_M / s;
        float run = -5.0f;
        s_ypos[d] = run;
        #pragma unroll 1
        for (int k = 0; k < KK; k++) {
            float h = __expf(uh[k] - m) * scale + 1e-4f;
            run += h;
            s_ypos[(k + 1) * DD + d] = run;
        }
        const float OFFS = 0.5411666430f;  // log(expm1(1 - 1e-4))
        #pragma unroll 1
        for (int k = 0; k <= KK; k++) {
            float v = us[k] + OFFS;
            float spv = fmaxf(v, 0.f) + __logf(1.f + __expf(-fabsf(v)));
            s_slp[k * DD + d] = spv + 1e-4f;
        }
    }
    __syncthreads();

    // ---- main loop: one warp per row, lane handles dims lane+32j ----
    const int lane = tid & 31;
    const int warp = (blockIdx.x * NTHREADS + tid) >> 5;
    const int nwarps = gridDim.x * (NTHREADS >> 5);
    const float LN2 = 0.69314718055994531f;

    for (int row = warp; row < n_rows; row += nwarps) {
        const float* xr = x + (size_t)row * DD;
        float prod = 1.0f;
        float yv[4];

        #pragma unroll
        for (int j = 0; j < 4; j++) {
            const int d = lane + 32 * j;
            float xv = xr[d];

            // level 1: LUT gives a conservative (low) bin base.
            // fmaf(xv,12.8,63) == floor((xv+5)*12.8) - 1 (safe low bias)
            int c = (int)fmaf(xv, 12.8f, 63.0f);
            c = max(0, min(c, NCELLS - 1));
            int base = (int)s_lut[c * DD + d];

            // level 2: 3 parallel indicator loads refine (imm offsets off xb)
            const float* xb = s_xpos + base * DD + d;
            int idx = base + (xv >= xb[1 * DD]) + (xv >= xb[2 * DD])
                           + (xv >= xb[3 * DD]);
            idx = min(idx, KK - 1);

            // level 3: all six params load imm-offset from one register o
            int o = idx * DD + d;
            float x0 = s_xpos[o];
            float x1 = s_xpos[o + DD];
            // cold fixup (knots/cell can exceed 3 for very narrow bins)
            while (idx < KK - 1 && xv >= x1) {
                idx++; o += DD;
                x0 = x1; x1 = s_xpos[o + DD];
            }
            float y0 = s_ypos[o - 2 * DD + (YPOS_OFF - XPOS_OFF) - (YPOS_OFF - XPOS_OFF) + 0]; // placeholder removed below
            y0 = sm[YPOS_OFF + o];
            float y1 = sm[YPOS_OFF + o + DD];
            float s0 = sm[SLP_OFF + o];
            float s1 = sm[SLP_OFF + o + DD];

            float ib;
            asm("rcp.approx.f32 %0, %1;" : "=f"(ib) : "f"(x1 - x0));
            float zr   = (xv - x0) * ib;
            float z    = fminf(fmaxf(zr, 0.f), 1.f);
            float bh   = y1 - y0;
            float bs   = bh * ib;
            float sqz  = z * z;
            float z1mz = z - sqz;
            float omz  = 1.f - z;
            float sq1  = omz * omz;

            float st  = (s0 + s1) - 2.f * bs;
            float den = fmaf(st, z1mz, bs);
            float num = bh * fmaf(s0, z1mz, bs * sqz);

            float r;
            asm("rcp.approx.f32 %0, %1;" : "=f"(r) : "f"(den));
            float yy = fmaf(num, r, y0);

            // derivative = bs^2 * arg / den^2 ; fold bs^2 via t = bs * (1/den)
            float arg = fmaf(s1, sqz, fmaf(s0, sq1, (bs + bs) * z1mz));
            float t   = bs * r;
            float deriv = (t * t) * arg;

            // out-of-range tails (P ~ 6e-7): linear extrapolation, edge slopes
            if (zr != z) {
                if (zr < 0.f) {
                    yy = fmaf(xv - x0, s0, y0);
                    deriv = s0;
                } else {
                    yy = fmaf(xv - x1, s1, y1);
                    deriv = s1;
                }
            }
            prod *= deriv;
            yv[j] = yy;
        }

        float* yr = y_out + (size_t)row * DD;
        #pragma unroll
        for (int j = 0; j < 4; j++) yr[lane + 32 * j] = yv[j];

        // one LG2 per 4 elements, then warp-sum; scale by ln2 once per row
        float ls = __log2f(prod);
        #pragma unroll
        for (int off = 16; off; off >>= 1)
            ls += __shfl_xor_sync(0xffffffffu, ls, off);
        if (lane == 0) ld_out[row] = ls * LN2;
    }
}

extern "C" void kernel_launch(void* const* d_in, const int* in_sizes, int n_in,
                              void* d_out, int out_size)
{
    const float* x  = (const float*)d_in[0];
    const float* sp = (const float*)d_in[1];
    const int n_rows = in_sizes[0] / DD;

    float* y_out  = (float*)d_out;
    float* ld_out = (float*)d_out + (size_t)n_rows * DD;

    cudaFuncSetAttribute(rqs_kernel, cudaFuncAttributeMaxDynamicSharedMemorySize,
                         SMEM_BYTES);
    rqs_kernel<<<NBLOCKS, NTHREADS, SMEM_BYTES>>>(x, sp, y_out, ld_out, n_rows);
}